// round 13
// baseline (speedup 1.0000x reference)
#include <cuda_runtime.h>
#include <cuda_bf16.h>
#include <cstdint>

#define NUx 100000
#define NIx 100000
#define NP  100096          // padded to multiple of 128
#define NEx 600000
#define D   128
#define DO  16
#define NB  391             // ceil(100000/256)
#define EB  2344            // ceil(600000/256)

// etype ids: 0 = uu (dst user, src user), 1 = ui (dst item, src user), 2 = iu (dst user, src item)
__device__ int g_deg[3][NP];        // padded entries stay 0 (never written)
__device__ int g_cur[3][NUx];
__device__ int g_rp[3][NUx + 1];
__device__ int g_col[3][NEx];
__device__ int g_bsum[3][512];
__device__ __nv_bfloat16 g_Ah[3][NP * D];   // hi bf16 of mean-agg
__device__ __nv_bfloat16 g_Al[3][NP * D];   // lo bf16 residual
__device__ __nv_bfloat16 g_Wt[3][2][D * D]; // [et 0:uu 1:iu 2:ui][0:hi 1:lo][n*128+k]
__device__ float g_p_user[NUx * DO];
__device__ float g_p_item[NIx * DO];

// ---------------- helpers ----------------
__device__ __forceinline__ uint32_t smem_u32(const void* p) {
    uint32_t a;
    asm("{ .reg .u64 t; cvta.to.shared.u64 t, %1; cvt.u32.u64 %0, t; }" : "=r"(a) : "l"(p));
    return a;
}
__device__ __forceinline__ void cpa16(uint32_t dst, const void* src) {
    asm volatile("cp.async.ca.shared.global [%0], [%1], 16;" :: "r"(dst), "l"(src));
}
#define CPA_COMMIT() asm volatile("cp.async.commit_group;" ::: "memory")
#define CPA_WAIT1()  asm volatile("cp.async.wait_group 1;" ::: "memory")
#define CPA_WAIT0()  asm volatile("cp.async.wait_group 0;" ::: "memory")

__device__ __forceinline__ void mma16816(float* c, const uint32_t* a, uint32_t b0, uint32_t b1) {
    asm volatile(
        "mma.sync.aligned.m16n8k16.row.col.f32.bf16.bf16.f32 "
        "{%0,%1,%2,%3}, {%4,%5,%6,%7}, {%8,%9}, {%0,%1,%2,%3};"
        : "+f"(c[0]), "+f"(c[1]), "+f"(c[2]), "+f"(c[3])
        : "r"(a[0]), "r"(a[1]), "r"(a[2]), "r"(a[3]), "r"(b0), "r"(b1));
}
__device__ __forceinline__ void ldsm4(uint32_t* r, uint32_t addr) {
    asm volatile("ldmatrix.sync.aligned.m8n8.x4.shared.b16 {%0,%1,%2,%3}, [%4];"
                 : "=r"(r[0]), "=r"(r[1]), "=r"(r[2]), "=r"(r[3]) : "r"(addr));
}
__device__ __forceinline__ void hilo(float v, unsigned short& h, unsigned short& l) {
    __nv_bfloat16 hb = __float2bfloat16(v);
    __nv_bfloat16 lb = __float2bfloat16(v - __bfloat162float(hb));
    h = __bfloat16_as_ushort(hb);
    l = __bfloat16_as_ushort(lb);
}

// ---------------- CSR build (batched over 3 etypes) ----------------
__global__ void k_zero_small() {
    int i = blockIdx.x * blockDim.x + threadIdx.x;
    if (i < NUx) {
#pragma unroll
        for (int y = 0; y < 3; y++) { g_deg[y][i] = 0; g_cur[y][i] = 0; }
    }
}
__global__ void k_degree(const int* __restrict__ duu, const int* __restrict__ dui,
                         const int* __restrict__ diu) {
    int e = blockIdx.x * blockDim.x + threadIdx.x;
    if (e < NEx) {
        atomicAdd(&g_deg[0][duu[e]], 1);
        atomicAdd(&g_deg[1][dui[e]], 1);
        atomicAdd(&g_deg[2][diu[e]], 1);
    }
}
__global__ void k_scan1() {
    __shared__ int s[256];
    int y = blockIdx.y, t = threadIdx.x;
    int i = blockIdx.x * 256 + t;
    int v = (i < NUx) ? g_deg[y][i] : 0;
    s[t] = v;
    __syncthreads();
#pragma unroll
    for (int off = 1; off < 256; off <<= 1) {
        int x = (t >= off) ? s[t - off] : 0;
        __syncthreads();
        s[t] += x;
        __syncthreads();
    }
    if (i < NUx) g_rp[y][i] = s[t] - v;
    if (t == 255) g_bsum[y][blockIdx.x] = s[255];
}
__global__ void k_scan2() {
    __shared__ int s[512];
    int y = blockIdx.x, t = threadIdx.x;
    int v = (t < NB) ? g_bsum[y][t] : 0;
    s[t] = v;
    __syncthreads();
#pragma unroll
    for (int off = 1; off < 512; off <<= 1) {
        int x = (t >= off) ? s[t - off] : 0;
        __syncthreads();
        s[t] += x;
        __syncthreads();
    }
    if (t < NB) g_bsum[y][t] = s[t] - v;
}
__global__ void k_scan3() {
    int y = blockIdx.y;
    int i = blockIdx.x * 256 + threadIdx.x;
    if (i < NUx) g_rp[y][i] += g_bsum[y][blockIdx.x];
    if (i == 0) g_rp[y][NUx] = NEx;
}
__global__ void k_fill(const int* __restrict__ suu, const int* __restrict__ duu,
                       const int* __restrict__ sui, const int* __restrict__ dui,
                       const int* __restrict__ siu, const int* __restrict__ diu) {
    int e = blockIdx.x * blockDim.x + threadIdx.x;
    if (e >= NEx) return;
    int y = blockIdx.y;
    const int* s; const int* d;
    if (y == 0)      { s = suu; d = duu; }
    else if (y == 1) { s = sui; d = dui; }
    else             { s = siu; d = diu; }
    int dn = d[e];
    int pos = g_rp[y][dn] + atomicAdd(&g_cur[y][dn], 1);
    g_col[y][pos] = s[e];
}

// ---------------- weight conversion: W[k][n] f32 -> Wt[n][k] bf16 hi/lo ----------------
__global__ void k_wcvt(const float* __restrict__ Wuu, const float* __restrict__ Wiu,
                       const float* __restrict__ Wui) {
    int et = blockIdx.y;
    int k = blockIdx.x;
    int n = threadIdx.x;
    const float* W = (et == 0) ? Wuu : (et == 1) ? Wiu : Wui;
    float v = W[k * 128 + n];
    unsigned short h, l;
    hilo(v, h, l);
    g_Wt[et][0][n * 128 + k] = __ushort_as_bfloat16(h);
    g_Wt[et][1][n * 128 + k] = __ushort_as_bfloat16(l);
}

// ---------------- aggregation: warp per node, mean -> bf16 hi/lo (unroll 8 for MLP) ----------------
__global__ void __launch_bounds__(256) k_agg(int et, const float4* __restrict__ emb) {
    int wid = threadIdx.x >> 5, lane = threadIdx.x & 31;
    int node = blockIdx.x * 8 + wid;
    if (node >= NP) return;
    float4 acc = make_float4(0.f, 0.f, 0.f, 0.f);
    if (node < NUx) {
        const int* rp  = g_rp[et];
        const int* col = g_col[et];
        int b = __ldg(&rp[node]), e = __ldg(&rp[node + 1]);
        int i = b;
        for (; i + 8 <= e; i += 8) {
            int c[8];
#pragma unroll
            for (int j = 0; j < 8; j++) c[j] = __ldg(&col[i + j]);
            float4 v[8];
#pragma unroll
            for (int j = 0; j < 8; j++) v[j] = emb[(size_t)c[j] * 32 + lane];
#pragma unroll
            for (int j = 0; j < 8; j++) {
                acc.x += v[j].x; acc.y += v[j].y; acc.z += v[j].z; acc.w += v[j].w;
            }
        }
        for (; i + 4 <= e; i += 4) {
            int c[4];
#pragma unroll
            for (int j = 0; j < 4; j++) c[j] = __ldg(&col[i + j]);
            float4 v[4];
#pragma unroll
            for (int j = 0; j < 4; j++) v[j] = emb[(size_t)c[j] * 32 + lane];
#pragma unroll
            for (int j = 0; j < 4; j++) {
                acc.x += v[j].x; acc.y += v[j].y; acc.z += v[j].z; acc.w += v[j].w;
            }
        }
        for (; i < e; i++) {
            int c = __ldg(&col[i]);
            float4 v = emb[(size_t)c * 32 + lane];
            acc.x += v.x; acc.y += v.y; acc.z += v.z; acc.w += v.w;
        }
        float s = 1.0f / (float)max(e - b, 1);
        acc.x *= s; acc.y *= s; acc.z *= s; acc.w *= s;
    }
    unsigned short h0, l0, h1, l1, h2, l2, h3, l3;
    hilo(acc.x, h0, l0); hilo(acc.y, h1, l1); hilo(acc.z, h2, l2); hilo(acc.w, h3, l3);
    uint2 hv = make_uint2((uint32_t)h0 | ((uint32_t)h1 << 16),
                          (uint32_t)h2 | ((uint32_t)h3 << 16));
    uint2 lv = make_uint2((uint32_t)l0 | ((uint32_t)l1 << 16),
                          (uint32_t)l2 | ((uint32_t)l3 << 16));
    ((uint2*)g_Ah[et])[(size_t)node * 32 + lane] = hv;
    ((uint2*)g_Al[et])[(size_t)node * 32 + lane] = lv;
}

// ---------------- layer-0 GEMM (HMMA + ldmatrix, 3-term split) + fused layer-1 proj ----------------
struct GP {
    const __nv_bfloat16 *Ah[2], *Al[2], *Wh[2], *Wl[2];
    const float *b0, *b1;
    const int *dg0, *dg1;
    const float *W1, *pb;
    float* P;
    int N;
};

// SMEM map (bytes): [0,81920) double-buffered groups {Ah,Al,Bh,Bl} x 10240
//                   [81920) b0 512 | [82432) b1 512 | [82944) mk0 512 | [83456) mk1 512
//                   [83968) W1 8192 | [92160) pb 64  -> total 92224
template <int NET>
__global__ void __launch_bounds__(256, 2) k_hgemm(GP gp) {
    extern __shared__ char S[];
    const int tid  = threadIdx.x;
    const int wid  = tid >> 5, lane = tid & 31;
    const int gId  = lane >> 2, t2 = (lane & 3) * 2;
    const int mrow = (wid & 3) * 32, ncol = (wid >> 2) * 64;
    const int mbase = blockIdx.x * 128;
    const uint32_t sb = smem_u32(S);

    float* sb0  = (float*)(S + 81920);
    float* sb1  = (float*)(S + 82432);
    float* smk0 = (float*)(S + 82944);
    float* smk1 = (float*)(S + 83456);
    float* sw1  = (float*)(S + 83968);
    float* spb  = (float*)(S + 92160);

    if (tid < 128) {
        sb0[tid]  = gp.b0[tid];
        smk0[tid] = (__ldg(&gp.dg0[mbase + tid]) > 0) ? 1.f : 0.f;
        if (NET == 2) {
            sb1[tid]  = gp.b1[tid];
            smk1[tid] = (__ldg(&gp.dg1[mbase + tid]) > 0) ? 1.f : 0.f;
        }
    }
    if (tid < 16) spb[tid] = gp.pb[tid];
#pragma unroll
    for (int i = 0; i < 2; i++) {
        int f = tid + i * 256;
        ((float4*)sw1)[f] = ((const float4*)gp.W1)[f];
    }

    float acc[2][8][4];
#pragma unroll
    for (int mi = 0; mi < 2; mi++)
#pragma unroll
        for (int ni = 0; ni < 8; ni++)
#pragma unroll
            for (int q = 0; q < 4; q++) acc[mi][ni][q] = 0.f;

    const int NG = NET * 4;
    auto load_group = [&](int buf, int g) {
        int et = g >> 2, kc = g & 3;
        const __nv_bfloat16* ah = gp.Ah[et];
        const __nv_bfloat16* al = gp.Al[et];
        const __nv_bfloat16* bh = gp.Wh[et];
        const __nv_bfloat16* bl = gp.Wl[et];
        uint32_t b0a = sb + buf * 40960;
#pragma unroll
        for (int i = 0; i < 2; i++) {
            int idx = tid + i * 256;
            int r = idx >> 2, s4 = idx & 3;
            size_t ga = (size_t)(mbase + r) * 128 + kc * 32 + s4 * 8;
            size_t gw = (size_t)r * 128 + kc * 32 + s4 * 8;
            uint32_t so = r * 80 + s4 * 16;
            cpa16(b0a + so,         ah + ga);
            cpa16(b0a + 10240 + so, al + ga);
            cpa16(b0a + 20480 + so, bh + gw);
            cpa16(b0a + 30720 + so, bl + gw);
        }
    };

    const int lr = lane & 7, lg = lane >> 3;
    const int arow = (lg & 1) * 8 + lr;
    const int brow = (lg >> 1) * 8 + lr;

    load_group(0, 0);
    CPA_COMMIT();
    for (int g = 0; g < NG; g++) {
        if (g + 1 < NG) { load_group((g + 1) & 1, g + 1); CPA_COMMIT(); CPA_WAIT1(); }
        else            { CPA_WAIT0(); }
        __syncthreads();
        const uint32_t Bs = sb + (g & 1) * 40960;
#pragma unroll
        for (int ks = 0; ks < 2; ks++) {
            const int kb = ks * 16;
            uint32_t ah0[4], ah1[4], al0[4], al1[4];
            uint32_t a0 = Bs + ((mrow + arow) * 40 + kb + (lg >> 1) * 8) * 2;
            uint32_t a1 = a0 + 16 * 80;
            ldsm4(ah0, a0);
            ldsm4(ah1, a1);
            ldsm4(al0, a0 + 10240);
            ldsm4(al1, a1 + 10240);
            const int bcol = kb + (lg & 1) * 8;
#pragma unroll
            for (int np = 0; np < 4; np++) {
                uint32_t bh[4], bl[4];
                uint32_t bo = Bs + 20480 + ((ncol + np * 16 + brow) * 40 + bcol) * 2;
                ldsm4(bh, bo);
                ldsm4(bl, bo + 10240);
                mma16816(acc[0][2 * np],     ah0, bh[0], bh[1]);
                mma16816(acc[1][2 * np],     ah1, bh[0], bh[1]);
                mma16816(acc[0][2 * np],     al0, bh[0], bh[1]);
                mma16816(acc[1][2 * np],     al1, bh[0], bh[1]);
                mma16816(acc[0][2 * np],     ah0, bl[0], bl[1]);
                mma16816(acc[1][2 * np],     ah1, bl[0], bl[1]);
                mma16816(acc[0][2 * np + 1], ah0, bh[2], bh[3]);
                mma16816(acc[1][2 * np + 1], ah1, bh[2], bh[3]);
                mma16816(acc[0][2 * np + 1], al0, bh[2], bh[3]);
                mma16816(acc[1][2 * np + 1], al1, bh[2], bh[3]);
                mma16816(acc[0][2 * np + 1], ah0, bl[2], bl[3]);
                mma16816(acc[1][2 * np + 1], ah1, bl[2], bl[3]);
            }
        }
        __syncthreads();
    }

    // epilogue: bias + mask + relu -> stg (f32, stride 132)
    float* stg = (float*)S;
#pragma unroll
    for (int mi = 0; mi < 2; mi++)
#pragma unroll
        for (int ni = 0; ni < 8; ni++) {
            int r0 = mrow + mi * 16 + gId, c0 = ncol + ni * 8 + t2;
            float m0a = smk0[r0], m0b = smk0[r0 + 8];
            float bx = sb0[c0], by = sb0[c0 + 1];
            float vx0 = acc[mi][ni][0] + m0a * bx, vy0 = acc[mi][ni][1] + m0a * by;
            float vx1 = acc[mi][ni][2] + m0b * bx, vy1 = acc[mi][ni][3] + m0b * by;
            if (NET == 2) {
                float m1a = smk1[r0], m1b = smk1[r0 + 8];
                float cx = sb1[c0], cy = sb1[c0 + 1];
                vx0 += m1a * cx; vy0 += m1a * cy;
                vx1 += m1b * cx; vy1 += m1b * cy;
            }
            *(float2*)&stg[r0 * 132 + c0]       = make_float2(fmaxf(vx0, 0.f), fmaxf(vy0, 0.f));
            *(float2*)&stg[(r0 + 8) * 132 + c0] = make_float2(fmaxf(vx1, 0.f), fmaxf(vy1, 0.f));
        }
    __syncthreads();

    // fused layer-1 projection: P[128x16] = stg @ W1 + pb
    {
        int cp = tid & 7;
        int rg = tid >> 3;
        float pax[4], pay[4];
#pragma unroll
        for (int j = 0; j < 4; j++) { pax[j] = spb[cp * 2]; pay[j] = spb[cp * 2 + 1]; }
#pragma unroll 4
        for (int k = 0; k < 128; k++) {
            float2 w = *(float2*)&sw1[k * 16 + cp * 2];
#pragma unroll
            for (int j = 0; j < 4; j++) {
                float h = stg[(rg * 4 + j) * 132 + k];
                pax[j] += h * w.x;
                pay[j] += h * w.y;
            }
        }
#pragma unroll
        for (int j = 0; j < 4; j++) {
            int gr = mbase + rg * 4 + j;
            if (gr < gp.N)
                *(float2*)&gp.P[(size_t)gr * 16 + cp * 2] = make_float2(pax[j], pay[j]);
        }
    }
}

// ---------------- layer-1 gather-combine, split in two halves (unrolled for MLP) ----------------
__global__ void k_l1i(float* __restrict__ out) {
    int t = blockIdx.x * blockDim.x + threadIdx.x;
    if (t >= NUx * 4) return;
    int n = t >> 2, lane = t & 3;
    int b2 = g_rp[2][n], e2 = g_rp[2][n + 1];
    float4 c = make_float4(0.f, 0.f, 0.f, 0.f);
    int i = b2;
    for (; i + 4 <= e2; i += 4) {
        int s0 = __ldg(&g_col[2][i]),     s1 = __ldg(&g_col[2][i + 1]);
        int s2 = __ldg(&g_col[2][i + 2]), s3 = __ldg(&g_col[2][i + 3]);
        float4 v0 = ((const float4*)g_p_item)[(size_t)s0 * 4 + lane];
        float4 v1 = ((const float4*)g_p_item)[(size_t)s1 * 4 + lane];
        float4 v2 = ((const float4*)g_p_item)[(size_t)s2 * 4 + lane];
        float4 v3 = ((const float4*)g_p_item)[(size_t)s3 * 4 + lane];
        c.x += (v0.x + v1.x) + (v2.x + v3.x);
        c.y += (v0.y + v1.y) + (v2.y + v3.y);
        c.z += (v0.z + v1.z) + (v2.z + v3.z);
        c.w += (v0.w + v1.w) + (v2.w + v3.w);
    }
    for (; i < e2; i++) {
        int s = __ldg(&g_col[2][i]);
        float4 v = ((const float4*)g_p_item)[(size_t)s * 4 + lane];
        c.x += v.x; c.y += v.y; c.z += v.z; c.w += v.w;
    }
    float i2 = 1.0f / (float)max(e2 - b2, 1);
    ((float4*)out)[t] = make_float4(c.x * i2, c.y * i2, c.z * i2, c.w * i2);
}
__global__ void k_l1u(float* __restrict__ out) {
    int t = blockIdx.x * blockDim.x + threadIdx.x;
    if (t >= NUx * 4) return;
    int n = t >> 2, lane = t & 3;
    int b0 = g_rp[0][n], e0 = g_rp[0][n + 1];
    float4 a = make_float4(0.f, 0.f, 0.f, 0.f);
    int i = b0;
    for (; i + 4 <= e0; i += 4) {
        int s0 = __ldg(&g_col[0][i]),     s1 = __ldg(&g_col[0][i + 1]);
        int s2 = __ldg(&g_col[0][i + 2]), s3 = __ldg(&g_col[0][i + 3]);
        float4 v0 = ((const float4*)g_p_user)[(size_t)s0 * 4 + lane];
        float4 v1 = ((const float4*)g_p_user)[(size_t)s1 * 4 + lane];
        float4 v2 = ((const float4*)g_p_user)[(size_t)s2 * 4 + lane];
        float4 v3 = ((const float4*)g_p_user)[(size_t)s3 * 4 + lane];
        a.x += (v0.x + v1.x) + (v2.x + v3.x);
        a.y += (v0.y + v1.y) + (v2.y + v3.y);
        a.z += (v0.z + v1.z) + (v2.z + v3.z);
        a.w += (v0.w + v1.w) + (v2.w + v3.w);
    }
    for (; i < e0; i++) {
        int s = __ldg(&g_col[0][i]);
        float4 v = ((const float4*)g_p_user)[(size_t)s * 4 + lane];
        a.x += v.x; a.y += v.y; a.z += v.z; a.w += v.w;
    }
    float i0 = 1.0f / (float)max(e0 - b0, 1);
    float4 o = ((float4*)out)[t];
    ((float4*)out)[t] = make_float4(o.x + a.x * i0, o.y + a.y * i0,
                                    o.z + a.z * i0, o.w + a.w * i0);
}

// ---------------- launch ----------------
extern "C" void kernel_launch(void* const* d_in, const int* in_sizes, int n_in,
                              void* d_out, int out_size) {
    const float* embed_user = (const float*)d_in[0];
    const float* embed_item = (const float*)d_in[1];
    const int* src_uu = (const int*)d_in[2];
    const int* dst_uu = (const int*)d_in[3];
    const int* src_ui = (const int*)d_in[4];
    const int* dst_ui = (const int*)d_in[5];
    const int* src_iu = (const int*)d_in[6];
    const int* dst_iu = (const int*)d_in[7];
    const float* W0_uu = (const float*)d_in[8];
    const float* b0_uu = (const float*)d_in[9];
    const float* W0_ui = (const float*)d_in[10];
    const float* b0_ui = (const float*)d_in[11];
    const float* W0_iu = (const float*)d_in[12];
    const float* b0_iu = (const float*)d_in[13];
    const float* W1_uu = (const float*)d_in[14];
    const float* b1_uu = (const float*)d_in[15];
    const float* W1_iu = (const float*)d_in[18];
    const float* b1_iu = (const float*)d_in[19];

    float *p_user, *p_item;
    int* degs;
    __nv_bfloat16 *ah, *al, *wt;
    cudaGetSymbolAddress((void**)&p_user, g_p_user);
    cudaGetSymbolAddress((void**)&p_item, g_p_item);
    cudaGetSymbolAddress((void**)&degs, g_deg);
    cudaGetSymbolAddress((void**)&ah, g_Ah);
    cudaGetSymbolAddress((void**)&al, g_Al);
    cudaGetSymbolAddress((void**)&wt, g_Wt);

    static cudaStream_t s1 = 0, s2 = 0;
    static cudaEvent_t eF = 0, eW = 0, eC = 0, eA0 = 0, eA2 = 0, eLi = 0;
    static bool init_done = false;
    const int SMEM_G = 92224;
    if (!init_done) {
        cudaStreamCreateWithFlags(&s1, cudaStreamNonBlocking);
        cudaStreamCreateWithFlags(&s2, cudaStreamNonBlocking);
        cudaEventCreateWithFlags(&eF, cudaEventDisableTiming);
        cudaEventCreateWithFlags(&eW, cudaEventDisableTiming);
        cudaEventCreateWithFlags(&eC, cudaEventDisableTiming);
        cudaEventCreateWithFlags(&eA0, cudaEventDisableTiming);
        cudaEventCreateWithFlags(&eA2, cudaEventDisableTiming);
        cudaEventCreateWithFlags(&eLi, cudaEventDisableTiming);
        cudaFuncSetAttribute(k_hgemm<2>, cudaFuncAttributeMaxDynamicSharedMemorySize, SMEM_G);
        cudaFuncSetAttribute(k_hgemm<1>, cudaFuncAttributeMaxDynamicSharedMemorySize, SMEM_G);
        init_done = true;
    }

    // fork
    cudaEventRecord(eF, 0);
    cudaStreamWaitEvent(s1, eF, 0);
    cudaStreamWaitEvent(s2, eF, 0);

    // s1: weight conversion (tiny)
    k_wcvt<<<dim3(128, 3), 128, 0, s1>>>(W0_uu, W0_iu, W0_ui);
    cudaEventRecord(eW, s1);

    // s0: batched CSR build (all 3 etypes), then agg0
    k_zero_small<<<NB, 256>>>();
    k_degree<<<EB, 256>>>(dst_uu, dst_ui, dst_iu);
    k_scan1<<<dim3(NB, 3), 256>>>();
    k_scan2<<<3, 512>>>();
    k_scan3<<<dim3(NB, 3), 256>>>();
    k_fill<<<dim3(EB, 3), 256>>>(src_uu, dst_uu, src_ui, dst_ui, src_iu, dst_iu);
    cudaEventRecord(eC, 0);
    k_agg<<<(NP + 7) / 8, 256>>>(0, (const float4*)embed_user);
    cudaEventRecord(eA0, 0);

    // s2: agg2 concurrent with agg0
    cudaStreamWaitEvent(s2, eC, 0);
    k_agg<<<(NP + 7) / 8, 256, 0, s2>>>(2, (const float4*)embed_item);
    cudaEventRecord(eA2, s2);

    const __nv_bfloat16* Ah0 = ah;
    const __nv_bfloat16* Ah1 = ah + (size_t)NP * D;
    const __nv_bfloat16* Ah2 = ah + (size_t)2 * NP * D;
    const __nv_bfloat16* Al0 = al;
    const __nv_bfloat16* Al1 = al + (size_t)NP * D;
    const __nv_bfloat16* Al2 = al + (size_t)2 * NP * D;
    const __nv_bfloat16* WhUU = wt;
    const __nv_bfloat16* WlUU = wt + 16384;
    const __nv_bfloat16* WhIU = wt + 2 * 16384;
    const __nv_bfloat16* WlIU = wt + 3 * 16384;
    const __nv_bfloat16* WhUI = wt + 4 * 16384;
    const __nv_bfloat16* WlUI = wt + 5 * 16384;

    // user GEMM on s0: needs agg0 (s0), agg2, weights
    cudaStreamWaitEvent(0, eW, 0);
    cudaStreamWaitEvent(0, eA2, 0);
    GP gu;
    gu.Ah[0] = Ah0; gu.Ah[1] = Ah2; gu.Al[0] = Al0; gu.Al[1] = Al2;
    gu.Wh[0] = WhUU; gu.Wh[1] = WhIU; gu.Wl[0] = WlUU; gu.Wl[1] = WlIU;
    gu.b0 = b0_uu; gu.b1 = b0_iu;
    gu.dg0 = degs; gu.dg1 = degs + 2 * NP;
    gu.W1 = W1_uu; gu.pb = b1_uu;
    gu.P = p_user; gu.N = NUx;
    k_hgemm<2><<<NP / 128, 256, SMEM_G>>>(gu);

    // s1: deferred agg1, item GEMM, l1i — hidden under user GEMM
    cudaStreamWaitEvent(s1, eA0, 0);
    cudaStreamWaitEvent(s1, eA2, 0);
    k_agg<<<(NP + 7) / 8, 256, 0, s1>>>(1, (const float4*)embed_user);
    GP gi;
    gi.Ah[0] = Ah1; gi.Ah[1] = Ah1; gi.Al[0] = Al1; gi.Al[1] = Al1;
    gi.Wh[0] = WhUI; gi.Wh[1] = WhUI; gi.Wl[0] = WlUI; gi.Wl[1] = WlUI;
    gi.b0 = b0_ui; gi.b1 = b0_ui;
    gi.dg0 = degs + NP; gi.dg1 = degs + NP;
    gi.W1 = W1_iu; gi.pb = b1_iu;
    gi.P = p_item; gi.N = NIx;
    k_hgemm<1><<<NP / 128, 256, SMEM_G, s1>>>(gi);
    k_l1i<<<(NUx * 4 + 255) / 256, 256, 0, s1>>>((float*)d_out);
    cudaEventRecord(eLi, s1);

    // critical-path tail
    cudaStreamWaitEvent(0, eLi, 0);
    k_l1u<<<(NUx * 4 + 255) / 256, 256>>>((float*)d_out);
}